// round 9
// baseline (speedup 1.0000x reference)
#include <cuda_runtime.h>
#include <cuda_fp16.h>
#include <cstdint>
#include <math.h>

// ---------------- problem constants ----------------
#define N_TOK 8192
#define DIM   1024
#define HID   2048
#define OUTD  1024
#define NEXP  8
#define NE9   9              // 8 routed + 1 shared
#define TOPK  2
#define EPSBN 1e-5f

// ---------------- GEMM tiling ----------------
#define BM 128
#define BN 128
#define BKC 64
#define NSTAGE 3
#define PITCH 72             // smem row pitch in halves (144B, ldmatrix conflict-free)
#define THREADS 288          // 8 consumer warps + 1 producer warp

#define ROWS_RTD (N_TOK*TOPK + NEXP*BM)     // 17408 routed (padded)
#define ROWS_TOT (ROWS_RTD + N_TOK)         // 25600 incl. shared segment

#define A_STG_H (128*PITCH)
#define STAGE_H (2*A_STG_H)
#define PAR_OFF_B (NSTAGE*STAGE_H*2)        // 110592 bytes
#define SMEM_BYTES (PAR_OFF_B + 3*128*4)    // 112128 bytes

// named barrier ids: ready[s]=1+s, free[s]=4+s, params=7
#define BAR_READY(s) (1 + (s))
#define BAR_FREE(s)  (4 + (s))

// ---------------- static device scratch ----------------
__device__ __half g_x16[(size_t)N_TOK * DIM];
__device__ __half g_w1[(size_t)NE9 * HID * DIM];
__device__ __half g_w2[(size_t)NE9 * HID * HID];
__device__ __half g_w3[(size_t)NE9 * OUTD * HID];
// bufA: L1 act (half); reused as L3 fp32 scratch after L2 (sizes match exactly)
__device__ __half g_bufA[(size_t)ROWS_TOT * HID];
__device__ __half g_bufB[(size_t)ROWS_TOT * HID];
__device__ float g_p1b[NE9 * HID], g_p1s[NE9 * HID], g_p1h[NE9 * HID];
__device__ float g_p2b[NE9 * HID], g_p2s[NE9 * HID], g_p2h[NE9 * HID];
__device__ float g_p3b[NE9 * OUTD];
__device__ int   g_cnt[NEXP];
__device__ int   g_off[NE9 + 1];
__device__ int   g_fill[NEXP];
__device__ int   g_tok2[N_TOK * TOPK];
__device__ float g_w2g[N_TOK * TOPK];
__device__ int   g_pos[N_TOK * TOPK];
__device__ int   g_rowtok[ROWS_TOT];

// ---------------- helpers (family-agnostic sm_80+ PTX) ----------------
__device__ __forceinline__ uint32_t smem_u32(const void* p) {
    uint32_t a;
    asm("{ .reg .u64 t; cvta.to.shared.u64 t, %1; cvt.u32.u64 %0, t; }" : "=r"(a) : "l"(p));
    return a;
}
__device__ __forceinline__ void cp16(uint32_t dst, const void* src, int szbytes) {
    asm volatile("cp.async.cg.shared.global [%0], [%1], 16, %2;"
                 :: "r"(dst), "l"(src), "r"(szbytes) : "memory");
}
template<int N> __device__ __forceinline__ void cp_wait() {
    asm volatile("cp.async.wait_group %0;" :: "n"(N) : "memory");
}
__device__ __forceinline__ void cp_commit() {
    asm volatile("cp.async.commit_group;" ::: "memory");
}
__device__ __forceinline__ void bar_sync(int id, int cnt) {
    asm volatile("bar.sync %0, %1;" :: "r"(id), "r"(cnt) : "memory");
}
__device__ __forceinline__ void bar_arrive(int id, int cnt) {
    asm volatile("bar.arrive %0, %1;" :: "r"(id), "r"(cnt) : "memory");
}
__device__ __forceinline__ void ldsm_x4(uint32_t addr, uint32_t* r) {
    asm volatile("ldmatrix.sync.aligned.m8n8.x4.shared.b16 {%0,%1,%2,%3}, [%4];"
                 : "=r"(r[0]), "=r"(r[1]), "=r"(r[2]), "=r"(r[3]) : "r"(addr));
}
__device__ __forceinline__ void mma_f16(float* c, const uint32_t* a, uint32_t b0, uint32_t b1) {
    asm volatile("mma.sync.aligned.m16n8k16.row.col.f32.f16.f16.f32 "
                 "{%0,%1,%2,%3}, {%4,%5,%6,%7}, {%8,%9}, {%0,%1,%2,%3};"
                 : "+f"(c[0]), "+f"(c[1]), "+f"(c[2]), "+f"(c[3])
                 : "r"(a[0]), "r"(a[1]), "r"(a[2]), "r"(a[3]), "r"(b0), "r"(b1));
}

// ---------------- merged convert + init (launch #1) ----------------
// segments (float4-unit thread indices), then rowtok/cnt init tail
#define CV0 ((size_t)N_TOK*DIM/4)
#define CV1 (CV0 + (size_t)NEXP*HID*DIM/4)
#define CV2 (CV1 + (size_t)HID*DIM/4)
#define CV3 (CV2 + (size_t)NEXP*HID*HID/4)
#define CV4 (CV3 + (size_t)HID*HID/4)
#define CV5 (CV4 + (size_t)NEXP*OUTD*HID/4)
#define CV6 (CV5 + (size_t)OUTD*HID/4)
#define CV7 (CV6 + (size_t)ROWS_TOT)
#define CV_BLOCKS ((CV7 + 255) / 256)

__device__ __forceinline__ void cvt4(const float* s, __half* d) {
    float4 v = *(const float4*)s;
    *(__half2*)(d)     = __floats2half2_rn(v.x, v.y);
    *(__half2*)(d + 2) = __floats2half2_rn(v.z, v.w);
}

__global__ void k_cvt_init(const float* __restrict__ x,
                           const float* __restrict__ W1, const float* __restrict__ sW1,
                           const float* __restrict__ W2, const float* __restrict__ sW2,
                           const float* __restrict__ W3, const float* __restrict__ sW3)
{
    size_t i = (size_t)blockIdx.x * 256 + threadIdx.x;
    if (i < CV0) {
        cvt4(x + i * 4, g_x16 + i * 4);
    } else if (i < CV1) {
        size_t j = (i - CV0) * 4; cvt4(W1 + j, g_w1 + j);
    } else if (i < CV2) {
        size_t j = (i - CV1) * 4; cvt4(sW1 + j, g_w1 + (size_t)NEXP*HID*DIM + j);
    } else if (i < CV3) {
        size_t j = (i - CV2) * 4; cvt4(W2 + j, g_w2 + j);
    } else if (i < CV4) {
        size_t j = (i - CV3) * 4; cvt4(sW2 + j, g_w2 + (size_t)NEXP*HID*HID + j);
    } else if (i < CV5) {
        size_t j = (i - CV4) * 4; cvt4(W3 + j, g_w3 + j);
    } else if (i < CV6) {
        size_t j = (i - CV5) * 4; cvt4(sW3 + j, g_w3 + (size_t)NEXP*OUTD*HID + j);
    } else if (i < CV7) {
        size_t j = i - CV6;
        g_rowtok[j] = -1;
        if (j < NEXP) g_cnt[j] = 0;
    }
}

// ---------------- combined epilogue params ----------------
__global__ void k_params(const float* b1, const float* g1, const float* be1,
                         const float* m1, const float* v1,
                         const float* b2, const float* g2, const float* be2,
                         const float* m2, const float* v2,
                         const float* b3,
                         const float* sb1, const float* sg1, const float* sbe1,
                         const float* sm1, const float* sv1,
                         const float* sb2, const float* sg2, const float* sbe2,
                         const float* sm2, const float* sv2,
                         const float* sb3)
{
    int idx = blockIdx.x * blockDim.x + threadIdx.x;
    if (idx >= NE9 * HID) return;
    int e = idx / HID, n = idx % HID;
    bool sh = (e == NEXP);
    size_t pe = (size_t)e * HID + n;
    {
        float bb = sh ? sb1[n] : b1[pe];
        float s = (sh ? sg1[n] : g1[pe]) * rsqrtf((sh ? sv1[n] : v1[pe]) + EPSBN);
        g_p1b[idx] = bb; g_p1s[idx] = s;
        g_p1h[idx] = fmaf(-(sh ? sm1[n] : m1[pe]), s, sh ? sbe1[n] : be1[pe]);
    }
    {
        float bb = sh ? sb2[n] : b2[pe];
        float s = (sh ? sg2[n] : g2[pe]) * rsqrtf((sh ? sv2[n] : v2[pe]) + EPSBN);
        g_p2b[idx] = bb; g_p2s[idx] = s;
        g_p2h[idx] = fmaf(-(sh ? sm2[n] : m2[pe]), s, sh ? sbe2[n] : be2[pe]);
    }
    if (n < OUTD) {
        g_p3b[e * OUTD + n] = sh ? sb3[n] : b3[(size_t)e * OUTD + n];
    }
}

// ---------------- routing ----------------
__global__ void k_gate(const float* __restrict__ x, const float* __restrict__ Wg) {
    int warp = threadIdx.x >> 5;
    int lane = threadIdx.x & 31;
    int t = blockIdx.x * 8 + warp;
    if (t >= N_TOK) return;
    const float* xr = x + (size_t)t * DIM;
    float acc[NEXP];
#pragma unroll
    for (int e = 0; e < NEXP; e++) acc[e] = 0.f;
    for (int d = lane; d < DIM; d += 32) {
        float xv = xr[d];
#pragma unroll
        for (int e = 0; e < NEXP; e++) acc[e] = fmaf(xv, Wg[e * DIM + d], acc[e]);
    }
#pragma unroll
    for (int e = 0; e < NEXP; e++)
#pragma unroll
        for (int s = 16; s > 0; s >>= 1) acc[e] += __shfl_xor_sync(0xffffffffu, acc[e], s);
    if (lane == 0) {
        float mx = acc[0];
#pragma unroll
        for (int e = 1; e < NEXP; e++) mx = fmaxf(mx, acc[e]);
        float p[NEXP], sum = 0.f;
#pragma unroll
        for (int e = 0; e < NEXP; e++) { p[e] = expf(acc[e] - mx); sum += p[e]; }
        float inv = 1.f / sum;
#pragma unroll
        for (int e = 0; e < NEXP; e++) p[e] *= inv;
        int i0 = 0;
#pragma unroll
        for (int e = 1; e < NEXP; e++) if (p[e] > p[i0]) i0 = e;
        int i1 = (i0 == 0) ? 1 : 0;
#pragma unroll
        for (int e = 0; e < NEXP; e++) if (e != i0 && p[e] > p[i1]) i1 = e;
        float den = p[i0] + p[i1] + 1e-20f;
        g_tok2[2 * t + 0] = i0; g_w2g[2 * t + 0] = p[i0] / den;
        g_tok2[2 * t + 1] = i1; g_w2g[2 * t + 1] = p[i1] / den;
        atomicAdd(&g_cnt[i0], 1);
        atomicAdd(&g_cnt[i1], 1);
    }
}

__global__ void k_offsets() {
    if (threadIdx.x == 0) {
        int o = 0;
        for (int e = 0; e < NEXP; e++) { g_off[e] = o; o += ((g_cnt[e] + BM - 1) / BM) * BM; }
        g_off[NEXP] = o;
        g_off[NE9]  = o + N_TOK;
    }
    if (threadIdx.x < NEXP) g_fill[threadIdx.x] = 0;
}

__global__ void k_scatter() {
    int t = blockIdx.x * blockDim.x + threadIdx.x;
    if (t >= N_TOK) return;
#pragma unroll
    for (int s = 0; s < TOPK; s++) {
        int e = g_tok2[2 * t + s];
        int pos = g_off[e] + atomicAdd(&g_fill[e], 1);
        g_rowtok[pos]    = t;
        g_pos[2 * t + s] = pos;
    }
    int sp = g_off[NEXP] + t;
    g_rowtok[sp] = t;
}

// ---------------- final combine ----------------
__global__ void k_combine(const float* __restrict__ C, float* __restrict__ out) {
    int idx = blockIdx.x * blockDim.x + threadIdx.x;
    if (idx >= N_TOK * (OUTD / 4)) return;
    int t  = idx / (OUTD / 4);
    int c4 = (idx % (OUTD / 4)) * 4;
    int p0 = g_pos[2 * t], p1 = g_pos[2 * t + 1];
    float w0 = g_w2g[2 * t], w1 = g_w2g[2 * t + 1];
    int sp = g_off[NEXP] + t;
    float4 a = *(const float4*)(C + (size_t)p0 * OUTD + c4);
    float4 b = *(const float4*)(C + (size_t)p1 * OUTD + c4);
    float4 s = *(const float4*)(C + (size_t)sp * OUTD + c4);
    float4 o;
    o.x = fmaf(w0, a.x, fmaf(w1, b.x, s.x));
    o.y = fmaf(w0, a.y, fmaf(w1, b.y, s.y));
    o.z = fmaf(w0, a.z, fmaf(w1, b.z, s.z));
    o.w = fmaf(w0, a.w, fmaf(w1, b.w, s.w));
    *(float4*)(out + (size_t)t * OUTD + c4) = o;
}

// ---------------- warp-specialized fp16 mma.sync fused GEMM ----------------
// 9 warps: warps 0-7 consumers (2x4, warp tile 64x32, m16n8k16), warp 8 producer
// (all cp.async). Stage handoff via named barriers ready[s]/free[s], count 288.
// Producer runs up to NSTAGE ahead, signals ready for chunk c-1 after wait_group<1>.
template<int EPI, bool GATHER>
__global__ void __launch_bounds__(THREADS, 2)
gemm_ws(const __half* __restrict__ X,
        const __half* __restrict__ Wb,
        const float* __restrict__ pb,
        const float* __restrict__ ps, const float* __restrict__ ph,
        void* __restrict__ outv,
        int Kd, int Hout, long wstride)
{
    extern __shared__ char smc[];
    int tid = threadIdx.x;
    int wid = tid >> 5;
    int lid = tid & 31;

    const int* off = g_off;
    int tileStart = blockIdx.y * BM;
    if (tileStart >= off[NE9]) return;      // uniform across CTA: no barriers touched
    int e = 0;
    while (e < NEXP && off[e + 1] <= tileStart) e++;
    const __half* W = Wb + (size_t)e * (size_t)wstride;
    int nbase = blockIdx.x * BN;
    uint32_t sb = smem_u32(smc);
    int Nc = Kd / BKC;

    if (wid == 8) {
        // ================= producer warp =================
        int r0 = lid * 4;                   // 4 consecutive rows per lane
        const __half* aptr[4]; int am[4];
        const __half* bptr[4];
        uint32_t adst[4], bdst[4];
#pragma unroll
        for (int i = 0; i < 4; i++) {
            int row = r0 + i;
            if (GATHER) {
                int tok = g_rowtok[tileStart + row];
                aptr[i] = X + (size_t)(tok >= 0 ? tok : 0) * Kd;
                am[i]   = (tok >= 0) ? 16 : 0;
            } else {
                aptr[i] = X + (size_t)(tileStart + row) * Kd;
                am[i]   = 16;
            }
            bptr[i] = W + (size_t)(nbase + row) * Kd;
            adst[i] = sb + (uint32_t)(row * PITCH) * 2u;
            bdst[i] = adst[i] + (uint32_t)A_STG_H * 2u;
        }
        for (int c = 0; c < Nc; c++) {
            int s = c % NSTAGE;
            if (c >= NSTAGE) bar_sync(BAR_FREE(s), THREADS);
            uint32_t so = (uint32_t)(s * STAGE_H) * 2u;
            int k0 = c * BKC;
#pragma unroll
            for (int i = 0; i < 4; i++) {
#pragma unroll
                for (int j = 0; j < 8; j++) {
                    cp16(adst[i] + so + j * 16, aptr[i] + k0 + j * 8, am[i]);
                    cp16(bdst[i] + so + j * 16, bptr[i] + k0 + j * 8, 16);
                }
            }
            cp_commit();
            if (c >= 1) { cp_wait<1>(); bar_arrive(BAR_READY((c - 1) % NSTAGE), THREADS); }
        }
        cp_wait<0>();
        bar_arrive(BAR_READY((Nc - 1) % NSTAGE), THREADS);
    } else {
        // ================= consumer warps 0-7 =================
        float* par_b  = (float*)(smc + PAR_OFF_B);
        float* par_sc = par_b + 128;
        float* par_sh = par_b + 256;
        if (tid < 128) {
            int n = e * Hout + nbase + tid;
            par_b[tid] = pb[n];
            if (EPI == 0) { par_sc[tid] = ps[n]; par_sh[tid] = ph[n]; }
        }
        bar_sync(7, 256);                    // consumers only

        float acc[16][4];
#pragma unroll
        for (int i = 0; i < 16; i++)
#pragma unroll
            for (int j = 0; j < 4; j++) acc[i][j] = 0.f;

        int warpM = wid & 1;
        int warpN = wid >> 1;
        int g = lid >> 2, t = lid & 3;
        int aRowSel = lid & 15;
        int aColSel = (lid >> 4) * 8;
        int bNoff   = (lid & 7) + ((lid >> 4) << 3);
        int bKoff   = ((lid >> 3) & 1) * 8;

        for (int c = 0; c < Nc; c++) {
            int s = c % NSTAGE;
            bar_sync(BAR_READY(s), THREADS);
            uint32_t As = sb + (uint32_t)(s * STAGE_H) * 2u;
            uint32_t Bs = As + (uint32_t)A_STG_H * 2u;
#pragma unroll
            for (int ks = 0; ks < 4; ks++) {
                uint32_t a[4][4];
#pragma unroll
                for (int mt = 0; mt < 4; mt++) {
                    uint32_t addr = As + (uint32_t)((warpM * 64 + mt * 16 + aRowSel) * PITCH
                                                    + ks * 16 + aColSel) * 2u;
                    ldsm_x4(addr, a[mt]);
                }
                uint32_t b[2][4];
#pragma unroll
                for (int ntp = 0; ntp < 2; ntp++) {
                    uint32_t addr = Bs + (uint32_t)((warpN * 32 + ntp * 16 + bNoff) * PITCH
                                                    + ks * 16 + bKoff) * 2u;
                    ldsm_x4(addr, b[ntp]);
                }
#pragma unroll
                for (int mt = 0; mt < 4; mt++) {
#pragma unroll
                    for (int nt = 0; nt < 4; nt++) {
                        uint32_t b0 = b[nt >> 1][(nt & 1) * 2];
                        uint32_t b1 = b[nt >> 1][(nt & 1) * 2 + 1];
                        mma_f16(acc[mt * 4 + nt], a[mt], b0, b1);
                    }
                }
            }
            if (c + NSTAGE < Nc) bar_arrive(BAR_FREE(s), THREADS);
        }

        // ---- epilogue ----
        __half* out16 = (__half*)outv;
        float*  outf  = (float*)outv;
#pragma unroll
        for (int mt = 0; mt < 4; mt++) {
            int rl0 = warpM * 64 + mt * 16 + g;
            int r0 = tileStart + rl0;
            int r1 = r0 + 8;
#pragma unroll
            for (int nt = 0; nt < 4; nt++) {
                float* c = acc[mt * 4 + nt];
                int colL = warpN * 32 + nt * 8 + 2 * t;
                int col = nbase + colL;
                if (EPI == 0) {
                    float b0 = par_b[colL], b1 = par_b[colL + 1];
                    float s0 = par_sc[colL], s1 = par_sc[colL + 1];
                    float h0 = par_sh[colL], h1 = par_sh[colL + 1];
                    __half2 o0 = __floats2half2_rn(
                        fmaf(fmaxf(c[0] + b0, 0.f), s0, h0),
                        fmaf(fmaxf(c[1] + b1, 0.f), s1, h1));
                    __half2 o1 = __floats2half2_rn(
                        fmaf(fmaxf(c[2] + b0, 0.f), s0, h0),
                        fmaf(fmaxf(c[3] + b1, 0.f), s1, h1));
                    *(__half2*)(out16 + (size_t)r0 * Hout + col) = o0;
                    *(__half2*)(out16 + (size_t)r1 * Hout + col) = o1;
                } else {
                    float b0 = par_b[colL], b1 = par_b[colL + 1];
                    float2 o0, o1;
                    o0.x = 1.f / (1.f + __expf(-(c[0] + b0)));
                    o0.y = 1.f / (1.f + __expf(-(c[1] + b1)));
                    o1.x = 1.f / (1.f + __expf(-(c[2] + b0)));
                    o1.y = 1.f / (1.f + __expf(-(c[3] + b1)));
                    *(float2*)(outf + (size_t)r0 * Hout + col) = o0;
                    *(float2*)(outf + (size_t)r1 * Hout + col) = o1;
                }
            }
        }
    }
}

// ---------------- launch ----------------
extern "C" void kernel_launch(void* const* d_in, const int* in_sizes, int n_in,
                              void* d_out, int out_size) {
    (void)in_sizes; (void)n_in; (void)out_size;

    const float* x   = (const float*)d_in[0];
    const float* Wg  = (const float*)d_in[1];
    const float* W1  = (const float*)d_in[2];
    const float* b1  = (const float*)d_in[3];
    const float* g1  = (const float*)d_in[4];
    const float* be1 = (const float*)d_in[5];
    const float* m1  = (const float*)d_in[6];
    const float* v1  = (const float*)d_in[7];
    const float* W2  = (const float*)d_in[8];
    const float* b2  = (const float*)d_in[9];
    const float* g2  = (const float*)d_in[10];
    const float* be2 = (const float*)d_in[11];
    const float* m2  = (const float*)d_in[12];
    const float* v2  = (const float*)d_in[13];
    const float* W3  = (const float*)d_in[14];
    const float* b3  = (const float*)d_in[15];
    const float* sW1 = (const float*)d_in[16];
    const float* sb1 = (const float*)d_in[17];
    const float* sg1 = (const float*)d_in[18];
    const float* sbe1= (const float*)d_in[19];
    const float* sm1 = (const float*)d_in[20];
    const float* sv1 = (const float*)d_in[21];
    const float* sW2 = (const float*)d_in[22];
    const float* sb2 = (const float*)d_in[23];
    const float* sg2 = (const float*)d_in[24];
    const float* sbe2= (const float*)d_in[25];
    const float* sm2 = (const float*)d_in[26];
    const float* sv2 = (const float*)d_in[27];
    const float* sW3 = (const float*)d_in[28];
    const float* sb3 = (const float*)d_in[29];
    float* out = (float*)d_out;

    __half *x16, *w1h, *w2h, *w3h, *bufA, *bufB;
    float *p1b, *p1s, *p1h, *p2b, *p2s, *p2h, *p3b;
    cudaGetSymbolAddress((void**)&x16,  g_x16);
    cudaGetSymbolAddress((void**)&w1h,  g_w1);
    cudaGetSymbolAddress((void**)&w2h,  g_w2);
    cudaGetSymbolAddress((void**)&w3h,  g_w3);
    cudaGetSymbolAddress((void**)&bufA, g_bufA);
    cudaGetSymbolAddress((void**)&bufB, g_bufB);
    cudaGetSymbolAddress((void**)&p1b,  g_p1b);
    cudaGetSymbolAddress((void**)&p1s,  g_p1s);
    cudaGetSymbolAddress((void**)&p1h,  g_p1h);
    cudaGetSymbolAddress((void**)&p2b,  g_p2b);
    cudaGetSymbolAddress((void**)&p2s,  g_p2s);
    cudaGetSymbolAddress((void**)&p2h,  g_p2h);
    cudaGetSymbolAddress((void**)&p3b,  g_p3b);

    float* scratch = (float*)bufA;   // L3 fp32 scratch aliases bufA (dead after L2)

    cudaFuncSetAttribute(gemm_ws<0, true>,  cudaFuncAttributeMaxDynamicSharedMemorySize, SMEM_BYTES);
    cudaFuncSetAttribute(gemm_ws<0, false>, cudaFuncAttributeMaxDynamicSharedMemorySize, SMEM_BYTES);
    cudaFuncSetAttribute(gemm_ws<1, false>, cudaFuncAttributeMaxDynamicSharedMemorySize, SMEM_BYTES);

    // launches 1-5 (so the 6th launch, captured by ncu -s 5 -c 1, is gemm1)
    k_cvt_init<<<(int)CV_BLOCKS, 256>>>(x, W1, sW1, W2, sW2, W3, sW3);
    k_params<<<(NE9 * HID + 255) / 256, 256>>>(
        b1, g1, be1, m1, v1, b2, g2, be2, m2, v2, b3,
        sb1, sg1, sbe1, sm1, sv1, sb2, sg2, sbe2, sm2, sv2, sb3);
    k_gate<<<N_TOK / 8, 256>>>(x, Wg);
    k_offsets<<<1, 32>>>();
    k_scatter<<<(N_TOK + 255) / 256, 256>>>();

    // unified 9-expert chain
    dim3 grid1(HID / BN,  ROWS_TOT / BM);
    dim3 grid3(OUTD / BN, ROWS_TOT / BM);
    gemm_ws<0, true><<<grid1, THREADS, SMEM_BYTES>>>(
        x16, w1h, p1b, p1s, p1h, bufA, DIM, HID, (long)HID * DIM);
    gemm_ws<0, false><<<grid1, THREADS, SMEM_BYTES>>>(
        bufA, w2h, p2b, p2s, p2h, bufB, HID, HID, (long)HID * HID);
    gemm_ws<1, false><<<grid3, THREADS, SMEM_BYTES>>>(
        bufB, w3h, p3b, nullptr, nullptr, scratch, HID, OUTD, (long)OUTD * HID);
    k_combine<<<(N_TOK * (OUTD / 4) + 255) / 256, 256>>>(scratch, out);
}

// round 11
// speedup vs baseline: 1.3332x; 1.3332x over previous
#include <cuda_runtime.h>
#include <cuda_fp16.h>
#include <cstdint>
#include <math.h>

// ---------------- problem constants ----------------
#define N_TOK 8192
#define DIM   1024
#define HID   2048
#define OUTD  1024
#define NEXP  8
#define NE9   9              // 8 routed + 1 shared
#define TOPK  2
#define EPSBN 1e-5f

// ---------------- GEMM tiling (R8-proven config) ----------------
#define BM 128
#define BN 128
#define BKC 64
#define NSTAGE 3
#define PITCH 72             // smem row pitch in halves (144B, ldmatrix conflict-free)

#define ROWS_RTD (N_TOK*TOPK + NEXP*BM)     // 17408 routed (padded)
#define ROWS_TOT (ROWS_RTD + N_TOK)         // 25600 incl. shared segment

#define A_STG_H (128*PITCH)
#define STAGE_H (2*A_STG_H)
#define PAR_OFF_B (NSTAGE*STAGE_H*2)        // 110592 bytes
#define SMEM_BYTES (PAR_OFF_B + 3*128*4)    // 112128 bytes

// converter CTAs packed into GEMM1's grid
#define CVT_Y 37                             // grid.y rows of converter CTAs (37*16=592)

// ---------------- static device scratch ----------------
__device__ __half g_x16[(size_t)N_TOK * DIM];
__device__ __half g_w1[(size_t)NE9 * HID * DIM];
__device__ __half g_w2[(size_t)NE9 * HID * HID];
__device__ __half g_w3[(size_t)NE9 * OUTD * HID];
// bufA: L1 act (half); reused as L3 fp32 scratch after L2 (byte sizes equal)
__device__ __half g_bufA[(size_t)ROWS_TOT * HID];
__device__ __half g_bufB[(size_t)ROWS_TOT * HID];
__device__ float g_p1b[NE9 * HID], g_p1s[NE9 * HID], g_p1h[NE9 * HID];
__device__ float g_p2b[NE9 * HID], g_p2s[NE9 * HID], g_p2h[NE9 * HID];
__device__ float g_p3b[NE9 * OUTD];
__device__ int   g_cnt[NEXP];
__device__ int   g_off[NE9 + 1];
__device__ int   g_fill[NEXP];
__device__ int   g_tok2[N_TOK * TOPK];
__device__ float g_w2g[N_TOK * TOPK];
__device__ int   g_pos[N_TOK * TOPK];
__device__ int   g_rowtok[ROWS_TOT];

// ---------------- helpers (family-agnostic sm_80+ PTX) ----------------
__device__ __forceinline__ uint32_t smem_u32(const void* p) {
    uint32_t a;
    asm("{ .reg .u64 t; cvta.to.shared.u64 t, %1; cvt.u32.u64 %0, t; }" : "=r"(a) : "l"(p));
    return a;
}
__device__ __forceinline__ void cp16(uint32_t dst, const void* src, int szbytes) {
    asm volatile("cp.async.cg.shared.global [%0], [%1], 16, %2;"
                 :: "r"(dst), "l"(src), "r"(szbytes) : "memory");
}
template<int N> __device__ __forceinline__ void cp_wait() {
    asm volatile("cp.async.wait_group %0;" :: "n"(N) : "memory");
}
__device__ __forceinline__ void cp_commit() {
    asm volatile("cp.async.commit_group;" ::: "memory");
}
__device__ __forceinline__ void ldsm_x4(uint32_t addr, uint32_t* r) {
    asm volatile("ldmatrix.sync.aligned.m8n8.x4.shared.b16 {%0,%1,%2,%3}, [%4];"
                 : "=r"(r[0]), "=r"(r[1]), "=r"(r[2]), "=r"(r[3]) : "r"(addr));
}
__device__ __forceinline__ void mma_f16(float* c, const uint32_t* a, uint32_t b0, uint32_t b1) {
    asm volatile("mma.sync.aligned.m16n8k16.row.col.f32.f16.f16.f32 "
                 "{%0,%1,%2,%3}, {%4,%5,%6,%7}, {%8,%9}, {%0,%1,%2,%3};"
                 : "+f"(c[0]), "+f"(c[1]), "+f"(c[2]), "+f"(c[3])
                 : "r"(a[0]), "r"(a[1]), "r"(a[2]), "r"(a[3]), "r"(b0), "r"(b1));
}
__device__ __forceinline__ void cvt4(const float* s, __half* d) {
    float4 v = *(const float4*)s;
    *(__half2*)(d)     = __floats2half2_rn(v.x, v.y);
    *(__half2*)(d + 2) = __floats2half2_rn(v.z, v.w);
}

// ---------------- k_prep: W1/sW1 convert + params + init (one launch) --------
#define PW1   ((size_t)NEXP*HID*DIM/4)                 // 4,194,304
#define PW1S  (PW1 + (size_t)HID*DIM/4)                // 4,718,592
#define PPAR  (PW1S + (size_t)NE9*HID)                 // + 18,432
#define PINIT (PPAR + (size_t)ROWS_TOT)                // + 25,600
#define PEND  (PINIT + NEXP)                           // + 8
#define PREP_BLOCKS ((PEND + 255) / 256)

__global__ void k_prep(const float* __restrict__ W1, const float* __restrict__ sW1,
                       const float* b1, const float* g1, const float* be1,
                       const float* m1, const float* v1,
                       const float* b2, const float* g2, const float* be2,
                       const float* m2, const float* v2,
                       const float* b3,
                       const float* sb1, const float* sg1, const float* sbe1,
                       const float* sm1, const float* sv1,
                       const float* sb2, const float* sg2, const float* sbe2,
                       const float* sm2, const float* sv2,
                       const float* sb3)
{
    size_t i = (size_t)blockIdx.x * 256 + threadIdx.x;
    if (i < PW1) {
        cvt4(W1 + i * 4, g_w1 + i * 4);
    } else if (i < PW1S) {
        size_t j = (i - PW1) * 4;
        cvt4(sW1 + j, g_w1 + (size_t)NEXP * HID * DIM + j);
    } else if (i < PPAR) {
        int idx = (int)(i - PW1S);
        int e = idx / HID, n = idx % HID;
        bool sh = (e == NEXP);
        size_t pe = (size_t)e * HID + n;
        {
            float bb = sh ? sb1[n] : b1[pe];
            float s = (sh ? sg1[n] : g1[pe]) * rsqrtf((sh ? sv1[n] : v1[pe]) + EPSBN);
            g_p1b[idx] = bb; g_p1s[idx] = s;
            g_p1h[idx] = fmaf(-(sh ? sm1[n] : m1[pe]), s, sh ? sbe1[n] : be1[pe]);
        }
        {
            float bb = sh ? sb2[n] : b2[pe];
            float s = (sh ? sg2[n] : g2[pe]) * rsqrtf((sh ? sv2[n] : v2[pe]) + EPSBN);
            g_p2b[idx] = bb; g_p2s[idx] = s;
            g_p2h[idx] = fmaf(-(sh ? sm2[n] : m2[pe]), s, sh ? sbe2[n] : be2[pe]);
        }
        if (n < OUTD) {
            g_p3b[e * OUTD + n] = sh ? sb3[n] : b3[(size_t)e * OUTD + n];
        }
    } else if (i < PINIT) {
        g_rowtok[i - PPAR] = -1;
    } else if (i < PEND) {
        int e = (int)(i - PINIT);
        g_cnt[e] = 0;
        g_fill[e] = 0;
    }
}

// ---------------- gate: softmax+top2 AND x -> fp16 conversion ----------------
__global__ void k_gate(const float* __restrict__ x, const float* __restrict__ Wg) {
    int warp = threadIdx.x >> 5;
    int lane = threadIdx.x & 31;
    int t = blockIdx.x * 8 + warp;
    if (t >= N_TOK) return;
    const float* xr = x + (size_t)t * DIM;
    __half* xo = g_x16 + (size_t)t * DIM;
    float acc[NEXP];
#pragma unroll
    for (int e = 0; e < NEXP; e++) acc[e] = 0.f;
#pragma unroll
    for (int it = 0; it < DIM / 128; it++) {
        int d = it * 128 + lane * 4;
        float4 xv = *(const float4*)(xr + d);
        *(__half2*)(xo + d)     = __floats2half2_rn(xv.x, xv.y);
        *(__half2*)(xo + d + 2) = __floats2half2_rn(xv.z, xv.w);
#pragma unroll
        for (int e = 0; e < NEXP; e++) {
            float4 w = *(const float4*)(Wg + (size_t)e * DIM + d);
            acc[e] = fmaf(xv.x, w.x, fmaf(xv.y, w.y, fmaf(xv.z, w.z, fmaf(xv.w, w.w, acc[e]))));
        }
    }
#pragma unroll
    for (int e = 0; e < NEXP; e++)
#pragma unroll
        for (int s = 16; s > 0; s >>= 1) acc[e] += __shfl_xor_sync(0xffffffffu, acc[e], s);
    if (lane == 0) {
        float mx = acc[0];
#pragma unroll
        for (int e = 1; e < NEXP; e++) mx = fmaxf(mx, acc[e]);
        float p[NEXP], sum = 0.f;
#pragma unroll
        for (int e = 0; e < NEXP; e++) { p[e] = expf(acc[e] - mx); sum += p[e]; }
        float inv = 1.f / sum;
#pragma unroll
        for (int e = 0; e < NEXP; e++) p[e] *= inv;
        int i0 = 0;
#pragma unroll
        for (int e = 1; e < NEXP; e++) if (p[e] > p[i0]) i0 = e;
        int i1 = (i0 == 0) ? 1 : 0;
#pragma unroll
        for (int e = 0; e < NEXP; e++) if (e != i0 && p[e] > p[i1]) i1 = e;
        float den = p[i0] + p[i1] + 1e-20f;
        g_tok2[2 * t + 0] = i0; g_w2g[2 * t + 0] = p[i0] / den;
        g_tok2[2 * t + 1] = i1; g_w2g[2 * t + 1] = p[i1] / den;
        atomicAdd(&g_cnt[i0], 1);
        atomicAdd(&g_cnt[i1], 1);
    }
}

// ---------------- scatter with inline padded-prefix offsets -------------------
__global__ void k_scatter() {
    int t = blockIdx.x * blockDim.x + threadIdx.x;
    if (t >= N_TOK) return;
    int offl[NE9];
    int o = 0;
#pragma unroll
    for (int e = 0; e < NEXP; e++) {
        offl[e] = o;
        o += ((g_cnt[e] + BM - 1) / BM) * BM;
    }
    offl[NEXP] = o;                      // shared segment start
    if (t == 0) {
#pragma unroll
        for (int e = 0; e < NE9; e++) g_off[e] = offl[e];
        g_off[NE9] = o + N_TOK;
    }
#pragma unroll
    for (int s = 0; s < TOPK; s++) {
        int e = g_tok2[2 * t + s];
        int pos = offl[e] + atomicAdd(&g_fill[e], 1);
        g_rowtok[pos]    = t;
        g_pos[2 * t + s] = pos;
    }
    g_rowtok[offl[NEXP] + t] = t;
}

// ---------------- final combine ----------------
__global__ void k_combine(const float* __restrict__ C, float* __restrict__ out) {
    int idx = blockIdx.x * blockDim.x + threadIdx.x;
    if (idx >= N_TOK * (OUTD / 4)) return;
    int t  = idx / (OUTD / 4);
    int c4 = (idx % (OUTD / 4)) * 4;
    int p0 = g_pos[2 * t], p1 = g_pos[2 * t + 1];
    float w0 = g_w2g[2 * t], w1 = g_w2g[2 * t + 1];
    int sp = g_off[NEXP] + t;
    float4 a = *(const float4*)(C + (size_t)p0 * OUTD + c4);
    float4 b = *(const float4*)(C + (size_t)p1 * OUTD + c4);
    float4 s = *(const float4*)(C + (size_t)sp * OUTD + c4);
    float4 o;
    o.x = fmaf(w0, a.x, fmaf(w1, b.x, s.x));
    o.y = fmaf(w0, a.y, fmaf(w1, b.y, s.y));
    o.z = fmaf(w0, a.z, fmaf(w1, b.z, s.z));
    o.w = fmaf(w0, a.w, fmaf(w1, b.w, s.w));
    *(float4*)(out + (size_t)t * OUTD + c4) = o;
}

// ---------------- fp16 mma.sync fused GEMM (R8 engine) + packed converters ---
// CTA tile 128x128, 8 warps (2x4), warp tile 64x32, m16n8k16 f16->f32,
// 3-stage cp.async pipeline, 2 CTAs/SM.
// If CVT: blockIdx.y < CVT_Y CTAs instead convert W2/sW2/W3/sW3 fp32->fp16
// (overlapped with the GEMM CTAs of the same launch).
// EPI 0: relu+BN -> __half store    EPI 1: sigmoid -> f32 row-indexed store
#define CB0 ((size_t)NEXP*HID*HID/4)
#define CB1 (CB0 + (size_t)HID*HID/4)
#define CB2 (CB1 + (size_t)NEXP*OUTD*HID/4)
#define CB3 (CB2 + (size_t)OUTD*HID/4)

template<int EPI, bool GATHER, bool CVT>
__global__ void __launch_bounds__(256, 2)
gemm_h(const __half* __restrict__ X,
       const __half* __restrict__ Wb,
       const float* __restrict__ pb,
       const float* __restrict__ ps, const float* __restrict__ ph,
       void* __restrict__ outv,
       int Kd, int Hout, long wstride,
       const float* __restrict__ cW2, const float* __restrict__ csW2,
       const float* __restrict__ cW3, const float* __restrict__ csW3)
{
    if (CVT && blockIdx.y < CVT_Y) {
        // converter role: strided fp32->fp16 over the W2/sW2/W3/sW3 blob
        size_t base = ((size_t)blockIdx.y * gridDim.x + blockIdx.x) * 256 + threadIdx.x;
        const size_t stride = (size_t)CVT_Y * 16 * 256;
        for (size_t i = base; i < CB3; i += stride) {
            if (i < CB0) {
                cvt4(cW2 + i * 4, g_w2 + i * 4);
            } else if (i < CB1) {
                size_t j = (i - CB0) * 4;
                cvt4(csW2 + j, g_w2 + (size_t)NEXP * HID * HID + j);
            } else if (i < CB2) {
                size_t j = (i - CB1) * 4;
                cvt4(cW3 + j, g_w3 + j);
            } else {
                size_t j = (i - CB2) * 4;
                cvt4(csW3 + j, g_w3 + (size_t)NEXP * OUTD * HID + j);
            }
        }
        return;
    }

    extern __shared__ char smc[];
    __half* sm = (__half*)smc;
    int tid = threadIdx.x;
    int wid = tid >> 5;
    int lid = tid & 31;

    const int* off = g_off;
    int tiley = CVT ? (int)blockIdx.y - CVT_Y : (int)blockIdx.y;
    int tileStart = tiley * BM;
    if (tileStart >= off[NE9]) return;
    int e = 0;
    while (e < NEXP && off[e + 1] <= tileStart) e++;
    const __half* W = Wb + (size_t)e * (size_t)wstride;
    int nbase = blockIdx.x * BN;

    float* par_b  = (float*)(smc + PAR_OFF_B);
    float* par_sc = par_b + 128;
    float* par_sh = par_b + 256;
    if (tid < 128) {
        int n = e * Hout + nbase + tid;
        par_b[tid] = pb[n];
        if (EPI == 0) { par_sc[tid] = ps[n]; par_sh[tid] = ph[n]; }
    }

    int lrow = tid >> 3;
    int lc   = (tid & 7) * 8;
    int arow[4]; unsigned amask = 0;
#pragma unroll
    for (int i = 0; i < 4; i++) {
        int r = lrow + 32 * i;
        if (GATHER) {
            int tok = g_rowtok[tileStart + r];
            arow[i] = (tok >= 0) ? tok : 0;
            if (tok >= 0) amask |= (1u << i);
        } else {
            arow[i] = tileStart + r;
            amask |= (1u << i);
        }
    }
    const __half* bbase = W + (size_t)(nbase + lrow) * Kd + lc;

    uint32_t sb = smem_u32(sm);
    uint32_t adst = sb + (uint32_t)(lrow * PITCH + lc) * 2u;
    uint32_t bdst = adst + (uint32_t)A_STG_H * 2u;

    float acc[16][4];
#pragma unroll
    for (int i = 0; i < 16; i++)
#pragma unroll
        for (int j = 0; j < 4; j++) acc[i][j] = 0.f;

    int warpM = wid & 1;
    int warpN = wid >> 1;
    int g = lid >> 2, t = lid & 3;

    int aRowSel = lid & 15;
    int aColSel = (lid >> 4) * 8;
    int bNoff   = (lid & 7) + ((lid >> 4) << 3);
    int bKoff   = ((lid >> 3) & 1) * 8;

    int Nc = Kd / BKC;

#pragma unroll
    for (int p = 0; p < 2; p++) {
        uint32_t so = (uint32_t)(p * STAGE_H) * 2u;
        int k0 = p * BKC;
#pragma unroll
        for (int i = 0; i < 4; i++) {
            cp16(adst + so + (uint32_t)(32 * i * PITCH) * 2u,
                 X + (size_t)arow[i] * Kd + k0 + lc, (amask >> i & 1) ? 16 : 0);
            cp16(bdst + so + (uint32_t)(32 * i * PITCH) * 2u,
                 bbase + (size_t)(32 * i) * Kd + k0, 16);
        }
        cp_commit();
    }

    int stage = 0;
    for (int c = 0; c < Nc; c++) {
        if (c + 1 < Nc) cp_wait<1>(); else cp_wait<0>();
        __syncthreads();

        if (c + 2 < Nc) {
            int sidx = (c + 2) % NSTAGE;
            uint32_t so = (uint32_t)(sidx * STAGE_H) * 2u;
            int k0 = (c + 2) * BKC;
#pragma unroll
            for (int i = 0; i < 4; i++) {
                cp16(adst + so + (uint32_t)(32 * i * PITCH) * 2u,
                     X + (size_t)arow[i] * Kd + k0 + lc, (amask >> i & 1) ? 16 : 0);
                cp16(bdst + so + (uint32_t)(32 * i * PITCH) * 2u,
                     bbase + (size_t)(32 * i) * Kd + k0, 16);
            }
            cp_commit();
        }

        uint32_t As = sb + (uint32_t)(stage * STAGE_H) * 2u;
        uint32_t Bs = As + (uint32_t)A_STG_H * 2u;
#pragma unroll
        for (int ks = 0; ks < 4; ks++) {
            uint32_t a[4][4];
#pragma unroll
            for (int mt = 0; mt < 4; mt++) {
                uint32_t addr = As + (uint32_t)((warpM * 64 + mt * 16 + aRowSel) * PITCH
                                                + ks * 16 + aColSel) * 2u;
                ldsm_x4(addr, a[mt]);
            }
            uint32_t b[2][4];
#pragma unroll
            for (int ntp = 0; ntp < 2; ntp++) {
                uint32_t addr = Bs + (uint32_t)((warpN * 32 + ntp * 16 + bNoff) * PITCH
                                                + ks * 16 + bKoff) * 2u;
                ldsm_x4(addr, b[ntp]);
            }
#pragma unroll
            for (int mt = 0; mt < 4; mt++) {
#pragma unroll
                for (int nt = 0; nt < 4; nt++) {
                    uint32_t b0 = b[nt >> 1][(nt & 1) * 2];
                    uint32_t b1 = b[nt >> 1][(nt & 1) * 2 + 1];
                    mma_f16(acc[mt * 4 + nt], a[mt], b0, b1);
                }
            }
        }
        stage = (stage + 1 == NSTAGE) ? 0 : stage + 1;
    }

    __half* out16 = (__half*)outv;
    float*  outf  = (float*)outv;
#pragma unroll
    for (int mt = 0; mt < 4; mt++) {
        int rl0 = warpM * 64 + mt * 16 + g;
        int r0 = tileStart + rl0;
        int r1 = r0 + 8;
#pragma unroll
        for (int nt = 0; nt < 4; nt++) {
            float* c = acc[mt * 4 + nt];
            int colL = warpN * 32 + nt * 8 + 2 * t;
            int col = nbase + colL;
            if (EPI == 0) {
                float b0 = par_b[colL], b1 = par_b[colL + 1];
                float s0 = par_sc[colL], s1 = par_sc[colL + 1];
                float h0 = par_sh[colL], h1 = par_sh[colL + 1];
                __half2 o0 = __floats2half2_rn(
                    fmaf(fmaxf(c[0] + b0, 0.f), s0, h0),
                    fmaf(fmaxf(c[1] + b1, 0.f), s1, h1));
                __half2 o1 = __floats2half2_rn(
                    fmaf(fmaxf(c[2] + b0, 0.f), s0, h0),
                    fmaf(fmaxf(c[3] + b1, 0.f), s1, h1));
                *(__half2*)(out16 + (size_t)r0 * Hout + col) = o0;
                *(__half2*)(out16 + (size_t)r1 * Hout + col) = o1;
            } else {
                float b0 = par_b[colL], b1 = par_b[colL + 1];
                float2 o0, o1;
                o0.x = 1.f / (1.f + __expf(-(c[0] + b0)));
                o0.y = 1.f / (1.f + __expf(-(c[1] + b1)));
                o1.x = 1.f / (1.f + __expf(-(c[2] + b0)));
                o1.y = 1.f / (1.f + __expf(-(c[3] + b1)));
                *(float2*)(outf + (size_t)r0 * Hout + col) = o0;
                *(float2*)(outf + (size_t)r1 * Hout + col) = o1;
            }
        }
    }
}

// ---------------- launch ----------------
extern "C" void kernel_launch(void* const* d_in, const int* in_sizes, int n_in,
                              void* d_out, int out_size) {
    (void)in_sizes; (void)n_in; (void)out_size;

    const float* x   = (const float*)d_in[0];
    const float* Wg  = (const float*)d_in[1];
    const float* W1  = (const float*)d_in[2];
    const float* b1  = (const float*)d_in[3];
    const float* g1  = (const float*)d_in[4];
    const float* be1 = (const float*)d_in[5];
    const float* m1  = (const float*)d_in[6];
    const float* v1  = (const float*)d_in[7];
    const float* W2  = (const float*)d_in[8];
    const float* b2  = (const float*)d_in[9];
    const float* g2  = (const float*)d_in[10];
    const float* be2 = (const float*)d_in[11];
    const float* m2  = (const float*)d_in[12];
    const float* v2  = (const float*)d_in[13];
    const float* W3  = (const float*)d_in[14];
    const float* b3  = (const float*)d_in[15];
    const float* sW1 = (const float*)d_in[16];
    const float* sb1 = (const float*)d_in[17];
    const float* sg1 = (const float*)d_in[18];
    const float* sbe1= (const float*)d_in[19];
    const float* sm1 = (const float*)d_in[20];
    const float* sv1 = (const float*)d_in[21];
    const float* sW2 = (const float*)d_in[22];
    const float* sb2 = (const float*)d_in[23];
    const float* sg2 = (const float*)d_in[24];
    const float* sbe2= (const float*)d_in[25];
    const float* sm2 = (const float*)d_in[26];
    const float* sv2 = (const float*)d_in[27];
    const float* sW3 = (const float*)d_in[28];
    const float* sb3 = (const float*)d_in[29];
    float* out = (float*)d_out;

    __half *x16, *w1h, *w2h, *w3h, *bufA, *bufB;
    float *p1b, *p1s, *p1h, *p2b, *p2s, *p2h, *p3b;
    cudaGetSymbolAddress((void**)&x16,  g_x16);
    cudaGetSymbolAddress((void**)&w1h,  g_w1);
    cudaGetSymbolAddress((void**)&w2h,  g_w2);
    cudaGetSymbolAddress((void**)&w3h,  g_w3);
    cudaGetSymbolAddress((void**)&bufA, g_bufA);
    cudaGetSymbolAddress((void**)&bufB, g_bufB);
    cudaGetSymbolAddress((void**)&p1b,  g_p1b);
    cudaGetSymbolAddress((void**)&p1s,  g_p1s);
    cudaGetSymbolAddress((void**)&p1h,  g_p1h);
    cudaGetSymbolAddress((void**)&p2b,  g_p2b);
    cudaGetSymbolAddress((void**)&p2s,  g_p2s);
    cudaGetSymbolAddress((void**)&p2h,  g_p2h);
    cudaGetSymbolAddress((void**)&p3b,  g_p3b);

    float* scratch = (float*)bufA;   // L3 fp32 scratch aliases bufA (dead after L2)

    cudaFuncSetAttribute(gemm_h<0, true, true>,   cudaFuncAttributeMaxDynamicSharedMemorySize, SMEM_BYTES);
    cudaFuncSetAttribute(gemm_h<0, false, false>, cudaFuncAttributeMaxDynamicSharedMemorySize, SMEM_BYTES);
    cudaFuncSetAttribute(gemm_h<1, false, false>, cudaFuncAttributeMaxDynamicSharedMemorySize, SMEM_BYTES);

    // 1) W1/sW1 convert + BN params + routing init (single launch)
    k_prep<<<(int)PREP_BLOCKS, 256>>>(W1, sW1,
        b1, g1, be1, m1, v1, b2, g2, be2, m2, v2, b3,
        sb1, sg1, sbe1, sm1, sv1, sb2, sg2, sbe2, sm2, sv2, sb3);
    // 2) gate (also converts x -> fp16)
    k_gate<<<N_TOK / 8, 256>>>(x, Wg);
    // 3) scatter (computes padded offsets inline, publishes g_off)
    k_scatter<<<(N_TOK + 255) / 256, 256>>>();

    // 4) GEMM1 with 592 packed converter CTAs for W2/sW2/W3/sW3
    dim3 grid1(HID / BN,  ROWS_TOT / BM + CVT_Y);
    gemm_h<0, true, true><<<grid1, 256, SMEM_BYTES>>>(
        x16, w1h, p1b, p1s, p1h, bufA, DIM, HID, (long)HID * DIM,
        W2, sW2, W3, sW3);
    // 5) GEMM2
    dim3 grid2(HID / BN,  ROWS_TOT / BM);
    gemm_h<0, false, false><<<grid2, 256, SMEM_BYTES>>>(
        bufA, w2h, p2b, p2s, p2h, bufB, HID, HID, (long)HID * HID,
        nullptr, nullptr, nullptr, nullptr);
    // 6) GEMM3 -> fp32 scratch
    dim3 grid3(OUTD / BN, ROWS_TOT / BM);
    gemm_h<1, false, false><<<grid3, 256, SMEM_BYTES>>>(
        bufB, w3h, p3b, nullptr, nullptr, scratch, HID, OUTD, (long)OUTD * HID,
        nullptr, nullptr, nullptr, nullptr);
    // 7) combine
    k_combine<<<(N_TOK * (OUTD / 4) + 255) / 256, 256>>>(scratch, out);
}